// round 14
// baseline (speedup 1.0000x reference)
#include <cuda_runtime.h>
#include <cuda_bf16.h>
#include <math.h>

#define N_NODES 50000
#define N_EDGES 800000
#define DIM 64

// ---- static scratch ----
__device__ __align__(16) float g_p[N_NODES * DIM];   // h @ w_flat^T
__device__ __align__(16) float g_A[N_NODES * 8];     // per-node unnormalized accumulator
__device__ float g_s[N_NODES];
__device__ float g_d[N_NODES];
__device__ float g_denom[N_NODES];

union F4U { float4 f; unsigned long long u[2]; };
union U64F2 { unsigned long long u; float f[2]; };

__device__ __forceinline__ unsigned long long f32x2_dup(float x) {
    unsigned long long r;
    unsigned int xi = __float_as_uint(x);
    asm("mov.b64 %0, {%1, %1};" : "=l"(r) : "r"(xi));
    return r;
}
__device__ __forceinline__ unsigned long long fma_f32x2(
    unsigned long long a, unsigned long long b, unsigned long long c) {
    unsigned long long d;
    asm("fma.rn.f32x2 %0, %1, %2, %3;" : "=l"(d) : "l"(a), "l"(b), "l"(c));
    return d;
}

// ============================================================================
// k_node: 64-node x 64-out tile, 128 threads = 2 threads per 8x8 microtile
// (split-K x2, combined via shfl_xor(8)). Doubles chip warps to ~21/SM to hide
// LDS/issue latency; proven FFMA2 mainloop + slab-W layout unchanged.
// Thread map: oq = tid&7, kq = (tid>>3)&1, nq = tid>>4 (0..7).
// ============================================================================
__global__ void __launch_bounds__(128, 5) k_node(
    const float* __restrict__ h, const float* __restrict__ w,
    const float* __restrict__ attn) {
    __shared__ float sHt[DIM * 64];    // sHt[i*64 + r] = h[n0+r][i]      (16KB)
    __shared__ float sWtS[8 * 516];    // sWtS[oq*516 + i*8 + k] = w[(8oq+k)*64+i]

    int tid = threadIdx.x;             // 0..127
    int n0 = blockIdx.x * 64;
    int nrem = N_NODES - n0;           // last block: 16

    // --- W fill: thread = (row o = tid&63, half = tid>>6), 8 float4 each ---
    {
        int o = tid & 63;
        int half = tid >> 6;
        int oq = o >> 3, k = o & 7;
        const float4* wrow = reinterpret_cast<const float4*>(w + o * DIM) + half * 8;
        float* slab = &sWtS[oq * 516 + k];
#pragma unroll
        for (int j = 0; j < 8; j++) {
            float4 v = __ldg(wrow + j);
            int i0 = half * 32 + j * 4;
            slab[(i0 + 0) * 8] = v.x;
            slab[(i0 + 1) * 8] = v.y;
            slab[(i0 + 2) * 8] = v.z;
            slab[(i0 + 3) * 8] = v.w;
        }
    }
    // --- H fill: thread = (row r = tid&63, half = tid>>6), 8 float4 each ---
    {
        int r = tid & 63;
        int half = tid >> 6;
        bool valid = (r < nrem);
        const float4* hrow = reinterpret_cast<const float4*>(
            h + (size_t)(n0 + (valid ? r : 0)) * DIM) + half * 8;
        float4 z = make_float4(0.f, 0.f, 0.f, 0.f);
#pragma unroll
        for (int j = 0; j < 8; j++) {
            float4 v = valid ? __ldg(hrow + j) : z;
            int c = half * 32 + j * 4;
            sHt[(c + 0) * 64 + r] = v.x;
            sHt[(c + 1) * 64 + r] = v.y;
            sHt[(c + 2) * 64 + r] = v.z;
            sHt[(c + 3) * 64 + r] = v.w;
        }
    }
    __syncthreads();

    // --- microtile with split-K: this thread does K slice [kq*32, kq*32+32) ---
    int oq = tid & 7;
    int kq = (tid >> 3) & 1;
    int nq = tid >> 4;                 // 0..7
    unsigned long long acc[8][4];
#pragma unroll
    for (int a = 0; a < 8; a++)
#pragma unroll
        for (int bp = 0; bp < 4; bp++) acc[a][bp] = 0ull;

    const float* wslab = &sWtS[oq * 516];
    int ibase = kq * 32;

#pragma unroll 4
    for (int ii = 0; ii < 32; ii++) {
        int i = ibase + ii;
        const float4* hp = reinterpret_cast<const float4*>(&sHt[i * 64 + 8 * nq]);
        float4 h0 = hp[0], h1 = hp[1];
        F4U w0, w1;
        w0.f = *reinterpret_cast<const float4*>(wslab + i * 8);
        w1.f = *reinterpret_cast<const float4*>(wslab + i * 8 + 4);
        unsigned long long wp[4] = {w0.u[0], w0.u[1], w1.u[0], w1.u[1]};
        float hv[8] = {h0.x, h0.y, h0.z, h0.w, h1.x, h1.y, h1.z, h1.w};
#pragma unroll
        for (int a = 0; a < 8; a++) {
            unsigned long long ha = f32x2_dup(hv[a]);
#pragma unroll
            for (int bp = 0; bp < 4; bp++)
                acc[a][bp] = fma_f32x2(ha, wp[bp], acc[a][bp]);
        }
    }

    // --- combine K halves: partner = lane ^ 8 (same warp); symmetric add ---
#pragma unroll
    for (int a = 0; a < 8; a++)
#pragma unroll
        for (int bp = 0; bp < 4; bp++) {
            U64F2 v; v.u = acc[a][bp];
            v.f[0] += __shfl_xor_sync(0xffffffffu, v.f[0], 8);
            v.f[1] += __shfl_xor_sync(0xffffffffu, v.f[1], 8);
            acc[a][bp] = v.u;
        }

    // --- store: kq=0 writes outs 8oq..+3 (bp 0,1); kq=1 writes 8oq+4..+7 ---
#pragma unroll
    for (int a = 0; a < 8; a++) {
        int rl = 8 * nq + a;
        if (rl < nrem) {
            F4U o0;
            o0.u[0] = acc[a][2 * kq];
            o0.u[1] = acc[a][2 * kq + 1];
            float* dst = &g_p[(size_t)(n0 + rl) * DIM + 8 * oq + 4 * kq];
            *reinterpret_cast<float4*>(dst) = o0.f;
        }
    }

    // --- attention scalars: threads 0..63 -> s, threads 64..127 -> d ---
    {
        int r = tid & 63;
        int which = tid >> 6;
        if (r < nrem) {
            const float* av = attn + which * 64;
            float acc_sd = 0.f;
#pragma unroll 8
            for (int i = 0; i < DIM; i++)
                acc_sd = fmaf(sHt[i * 64 + r], __ldg(av + i), acc_sd);
            int n = n0 + r;
            if (which == 0) { g_s[n] = acc_sd; g_denom[n] = 0.0f; }
            else            { g_d[n] = acc_sd; }
        }
    }
    if (tid * 4 < nrem * 8) {
        *reinterpret_cast<float4*>(&g_A[n0 * 8 + tid * 4]) =
            make_float4(0.f, 0.f, 0.f, 0.f);
    }
}

// ============================================================================
// Fused edge pass (R12-proven scalar form): denom[dn] += ex ;
// A[dn] += ex * p[sn, 8r..8r+7].
// ============================================================================
__global__ void k_edge(const int* __restrict__ src, const int* __restrict__ dst,
                       const int* __restrict__ we) {
    int e = blockIdx.x * blockDim.x + threadIdx.x;
    if (e >= N_EDGES) return;
    int sn = src[e], dn = dst[e], r = we[e];
    float x = __ldg(&g_s[sn]) + __ldg(&g_d[dn]);
    float v = (x > 0.0f) ? x : 0.01f * x;
    float ex = __expf(v);
    const float4* pr = reinterpret_cast<const float4*>(g_p + sn * DIM + r * 8);
    float4 p0 = __ldg(pr), p1 = __ldg(pr + 1);
    atomicAdd(&g_denom[dn], ex);
    float4* arow = reinterpret_cast<float4*>(g_A + dn * 8);
    atomicAdd(&arow[0], make_float4(ex * p0.x, ex * p0.y, ex * p0.z, ex * p0.w));
    atomicAdd(&arow[1], make_float4(ex * p1.x, ex * p1.y, ex * p1.z, ex * p1.w));
}

// ============================================================================
// Expand (proven): out[n, o] = w_comp[o & 7] * A[n, o >> 3] / max(denom, 1e-38).
// ============================================================================
#define HALF_F4 (N_NODES * 8)
__global__ void k_expand(const float* __restrict__ w_comp, float* __restrict__ out) {
    int t = blockIdx.x * blockDim.x + threadIdx.x;
    if (t >= HALF_F4) return;
    float4 wc0 = __ldg(reinterpret_cast<const float4*>(w_comp));
    float4 wc1 = __ldg(reinterpret_cast<const float4*>(w_comp) + 1);
#pragma unroll
    for (int half = 0; half < 2; half++) {
        int t4 = t + half * HALF_F4;
        int n = t4 >> 4;
        int k = t4 & 15;
        float inv = __fdividef(1.0f, fmaxf(g_denom[n], 1e-38f));
        float a = g_A[n * 8 + (k >> 1)] * inv;
        float4 wc = (k & 1) ? wc1 : wc0;
        reinterpret_cast<float4*>(out)[t4] =
            make_float4(a * wc.x, a * wc.y, a * wc.z, a * wc.w);
    }
}

extern "C" void kernel_launch(void* const* d_in, const int* in_sizes, int n_in,
                              void* d_out, int out_size) {
    const float* h      = (const float*)d_in[0];
    const int*   src    = (const int*)d_in[1];
    const int*   dst    = (const int*)d_in[2];
    const int*   we     = (const int*)d_in[3];
    const float* w      = (const float*)d_in[4];
    const float* w_comp = (const float*)d_in[5];
    const float* attn   = (const float*)d_in[6];
    float* out = (float*)d_out;
    (void)in_sizes; (void)n_in; (void)out_size;

    k_node<<<(N_NODES + 63) / 64, 128>>>(h, w, attn);
    k_edge<<<(N_EDGES + 255) / 256, 256>>>(src, dst, we);
    k_expand<<<(HALF_F4 + 255) / 256, 256>>>(w_comp, out);
}

// round 16
// speedup vs baseline: 1.2467x; 1.2467x over previous
#include <cuda_runtime.h>
#include <cuda_bf16.h>
#include <math.h>
#include <stdint.h>

#define N_NODES 50000
#define N_EDGES 800000
#define DIM 64
#define TILE_M 64

// ---- static scratch ----
__device__ __align__(16) float g_p[N_NODES * DIM];   // h @ w_flat^T
__device__ __align__(16) float g_A[N_NODES * 8];     // per-node unnormalized accumulator
__device__ float g_s[N_NODES];
__device__ float g_d[N_NODES];
__device__ float g_denom[N_NODES];

__device__ __forceinline__ uint32_t pack_bf16x2(float lo, float hi_el) {
    // low 16 bits = first (even col) element
    unsigned short a = __bfloat16_as_ushort(__float2bfloat16(lo));
    unsigned short b = __bfloat16_as_ushort(__float2bfloat16(hi_el));
    return ((uint32_t)b << 16) | (uint32_t)a;
}
__device__ __forceinline__ float bf_val(float x) {
    return __bfloat162float(__float2bfloat16(x));
}
__device__ __forceinline__ void mma_bf16(float c[4], uint32_t a0, uint32_t a1,
                                         uint32_t a2, uint32_t a3,
                                         uint32_t b0, uint32_t b1) {
    asm volatile(
        "mma.sync.aligned.m16n8k16.row.col.f32.bf16.bf16.f32 "
        "{%0,%1,%2,%3}, {%4,%5,%6,%7}, {%8,%9}, {%0,%1,%2,%3};"
        : "+f"(c[0]), "+f"(c[1]), "+f"(c[2]), "+f"(c[3])
        : "r"(a0), "r"(a1), "r"(a2), "r"(a3), "r"(b0), "r"(b1));
}

// ============================================================================
// k_node: 64-node x 64-out tile via bf16-split tensor-core MMA
// (h_hi*w_hi + h_hi*w_lo + h_lo*w_hi, f32 accum). 128 threads = 4 warps,
// warp w owns rows 16w..16w+15. Row stride 36 u32 (72 bf16) => all fragment
// LDS hit distinct banks (bank = 4*(lane>>2) + (lane&3)).
// s/d in fp32 during the h fill; zero denom/A.
// ============================================================================
__global__ void __launch_bounds__(128) k_node(
    const float* __restrict__ h, const float* __restrict__ w,
    const float* __restrict__ attn) {
    __shared__ uint32_t sH_hi[TILE_M * 36];   // 9KB each
    __shared__ uint32_t sH_lo[TILE_M * 36];
    __shared__ uint32_t sW_hi[64 * 36];
    __shared__ uint32_t sW_lo[64 * 36];

    int tid = threadIdx.x;
    int n0 = blockIdx.x * TILE_M;
    int nrem = N_NODES - n0;              // last block: 16

    // --- h fill + s/d: 2 threads per row, 32 cols each ---
    {
        int row = tid >> 1;
        int half = tid & 1;
        bool valid = (row < nrem);
        const float4* hrow = reinterpret_cast<const float4*>(
            h + (size_t)(n0 + (valid ? row : 0)) * DIM) + half * 8;
        float s = 0.f, d = 0.f;
#pragma unroll
        for (int c4 = 0; c4 < 8; c4++) {
            float4 v = valid ? __ldg(hrow + c4) : make_float4(0.f, 0.f, 0.f, 0.f);
            int cb = half * 32 + c4 * 4;
            s = fmaf(v.x, __ldg(attn + cb), s);
            s = fmaf(v.y, __ldg(attn + cb + 1), s);
            s = fmaf(v.z, __ldg(attn + cb + 2), s);
            s = fmaf(v.w, __ldg(attn + cb + 3), s);
            d = fmaf(v.x, __ldg(attn + 64 + cb), d);
            d = fmaf(v.y, __ldg(attn + 64 + cb + 1), d);
            d = fmaf(v.z, __ldg(attn + 64 + cb + 2), d);
            d = fmaf(v.w, __ldg(attn + 64 + cb + 3), d);
            int idx = row * 36 + cb / 2;
            sH_hi[idx]     = pack_bf16x2(v.x, v.y);
            sH_hi[idx + 1] = pack_bf16x2(v.z, v.w);
            sH_lo[idx]     = pack_bf16x2(v.x - bf_val(v.x), v.y - bf_val(v.y));
            sH_lo[idx + 1] = pack_bf16x2(v.z - bf_val(v.z), v.w - bf_val(v.w));
        }
        s += __shfl_xor_sync(0xffffffffu, s, 1);
        d += __shfl_xor_sync(0xffffffffu, d, 1);
        if (half == 0 && valid) {
            int n = n0 + row;
            g_s[n] = s;
            g_d[n] = d;
            g_denom[n] = 0.0f;
            float4 z = make_float4(0.f, 0.f, 0.f, 0.f);
            *reinterpret_cast<float4*>(&g_A[n * 8]) = z;
            *reinterpret_cast<float4*>(&g_A[n * 8 + 4]) = z;
        }
    }
    // --- w fill: 2 threads per row (64 rows, 128 threads) ---
    {
        int row = tid >> 1;
        int half = tid & 1;
        const float4* wrow = reinterpret_cast<const float4*>(w + row * DIM) + half * 8;
#pragma unroll
        for (int c4 = 0; c4 < 8; c4++) {
            float4 v = __ldg(wrow + c4);
            int cb = half * 32 + c4 * 4;
            int idx = row * 36 + cb / 2;
            sW_hi[idx]     = pack_bf16x2(v.x, v.y);
            sW_hi[idx + 1] = pack_bf16x2(v.z, v.w);
            sW_lo[idx]     = pack_bf16x2(v.x - bf_val(v.x), v.y - bf_val(v.y));
            sW_lo[idx + 1] = pack_bf16x2(v.z - bf_val(v.z), v.w - bf_val(v.w));
        }
    }
    __syncthreads();

    // --- tensor-core mainloop ---
    int lane = tid & 31;
    int wid = tid >> 5;                  // 0..3
    int g = lane >> 2;                   // 0..7
    int q = lane & 3;                    // 0..3
    int row0 = wid * 16 + g;

    float acc[8][4];
#pragma unroll
    for (int nt = 0; nt < 8; nt++)
#pragma unroll
        for (int j = 0; j < 4; j++) acc[nt][j] = 0.0f;

#pragma unroll
    for (int kt = 0; kt < 4; kt++) {
        int ai = row0 * 36 + kt * 8 + q;
        uint32_t ah0 = sH_hi[ai],       ah1 = sH_hi[ai + 8 * 36];
        uint32_t ah2 = sH_hi[ai + 4],   ah3 = sH_hi[ai + 4 + 8 * 36];
        uint32_t al0 = sH_lo[ai],       al1 = sH_lo[ai + 8 * 36];
        uint32_t al2 = sH_lo[ai + 4],   al3 = sH_lo[ai + 4 + 8 * 36];
#pragma unroll
        for (int nt = 0; nt < 8; nt++) {
            int bi = (nt * 8 + g) * 36 + kt * 8 + q;
            uint32_t bh0 = sW_hi[bi], bh1 = sW_hi[bi + 4];
            uint32_t bl0 = sW_lo[bi], bl1 = sW_lo[bi + 4];
            mma_bf16(acc[nt], ah0, ah1, ah2, ah3, bh0, bh1);
            mma_bf16(acc[nt], ah0, ah1, ah2, ah3, bl0, bl1);
            mma_bf16(acc[nt], al0, al1, al2, al3, bh0, bh1);
        }
    }

    // --- store p ---
    {
        int r1 = row0, r2 = row0 + 8;
        bool v1 = (r1 < nrem), v2 = (r2 < nrem);
        float* base1 = &g_p[(size_t)(n0 + r1) * DIM];
        float* base2 = &g_p[(size_t)(n0 + r2) * DIM];
#pragma unroll
        for (int nt = 0; nt < 8; nt++) {
            int col = nt * 8 + q * 2;
            if (v1) *reinterpret_cast<float2*>(base1 + col) =
                        make_float2(acc[nt][0], acc[nt][1]);
            if (v2) *reinterpret_cast<float2*>(base2 + col) =
                        make_float2(acc[nt][2], acc[nt][3]);
        }
    }
}

// ============================================================================
// Fused edge pass (R12-proven): denom[dn] += ex ; A[dn] += ex * p[sn, 8r..8r+7].
// ============================================================================
__global__ void k_edge(const int* __restrict__ src, const int* __restrict__ dst,
                       const int* __restrict__ we) {
    int e = blockIdx.x * blockDim.x + threadIdx.x;
    if (e >= N_EDGES) return;
    int sn = src[e], dn = dst[e], r = we[e];
    float x = __ldg(&g_s[sn]) + __ldg(&g_d[dn]);
    float v = (x > 0.0f) ? x : 0.01f * x;
    float ex = __expf(v);
    const float4* pr = reinterpret_cast<const float4*>(g_p + sn * DIM + r * 8);
    float4 p0 = __ldg(pr), p1 = __ldg(pr + 1);
    atomicAdd(&g_denom[dn], ex);
    float4* arow = reinterpret_cast<float4*>(g_A + dn * 8);
    atomicAdd(&arow[0], make_float4(ex * p0.x, ex * p0.y, ex * p0.z, ex * p0.w));
    atomicAdd(&arow[1], make_float4(ex * p1.x, ex * p1.y, ex * p1.z, ex * p1.w));
}

// ============================================================================
// Expand (proven): out[n, o] = w_comp[o & 7] * A[n, o >> 3] / max(denom, 1e-38).
// ============================================================================
#define HALF_F4 (N_NODES * 8)
__global__ void k_expand(const float* __restrict__ w_comp, float* __restrict__ out) {
    int t = blockIdx.x * blockDim.x + threadIdx.x;
    if (t >= HALF_F4) return;
    float4 wc0 = __ldg(reinterpret_cast<const float4*>(w_comp));
    float4 wc1 = __ldg(reinterpret_cast<const float4*>(w_comp) + 1);
#pragma unroll
    for (int half = 0; half < 2; half++) {
        int t4 = t + half * HALF_F4;
        int n = t4 >> 4;
        int k = t4 & 15;
        float inv = __fdividef(1.0f, fmaxf(g_denom[n], 1e-38f));
        float a = g_A[n * 8 + (k >> 1)] * inv;
        float4 wc = (k & 1) ? wc1 : wc0;
        reinterpret_cast<float4*>(out)[t4] =
            make_float4(a * wc.x, a * wc.y, a * wc.z, a * wc.w);
    }
}

extern "C" void kernel_launch(void* const* d_in, const int* in_sizes, int n_in,
                              void* d_out, int out_size) {
    const float* h      = (const float*)d_in[0];
    const int*   src    = (const int*)d_in[1];
    const int*   dst    = (const int*)d_in[2];
    const int*   we     = (const int*)d_in[3];
    const float* w      = (const float*)d_in[4];
    const float* w_comp = (const float*)d_in[5];
    const float* attn   = (const float*)d_in[6];
    float* out = (float*)d_out;
    (void)in_sizes; (void)n_in; (void)out_size;

    k_node<<<(N_NODES + TILE_M - 1) / TILE_M, 128>>>(h, w, attn);
    k_edge<<<(N_EDGES + 255) / 256, 256>>>(src, dst, we);
    k_expand<<<(HALF_F4 + 255) / 256, 256>>>(w_comp, out);
}

// round 17
// speedup vs baseline: 1.3118x; 1.0522x over previous
#include <cuda_runtime.h>
#include <cuda_bf16.h>
#include <math.h>
#include <stdint.h>

#define N_NODES 50000
#define N_EDGES 800000
#define DIM 64
#define TILE_M 64

// ---- static scratch ----
__device__ __align__(16) float g_p[N_NODES * DIM];   // h @ w_flat^T
__device__ __align__(16) float g_A[N_NODES * 8];     // per-node unnormalized accumulator
__device__ float g_s[N_NODES];
__device__ float g_d[N_NODES];
__device__ float g_denom[N_NODES];
// precomputed w bf16 hi/lo smem image (row stride 36 u32)
__device__ __align__(16) uint32_t g_wimg_hi[64 * 36];
__device__ __align__(16) uint32_t g_wimg_lo[64 * 36];

__device__ __forceinline__ uint32_t pack_bf16x2(float even, float odd) {
    uint32_t p;
    asm("cvt.rn.bf16x2.f32 %0, %1, %2;" : "=r"(p) : "f"(odd), "f"(even));
    return p;   // low 16 bits = even element
}
__device__ __forceinline__ void mma_bf16(float c[4], uint32_t a0, uint32_t a1,
                                         uint32_t a2, uint32_t a3,
                                         uint32_t b0, uint32_t b1) {
    asm volatile(
        "mma.sync.aligned.m16n8k16.row.col.f32.bf16.bf16.f32 "
        "{%0,%1,%2,%3}, {%4,%5,%6,%7}, {%8,%9}, {%0,%1,%2,%3};"
        : "+f"(c[0]), "+f"(c[1]), "+f"(c[2]), "+f"(c[3])
        : "r"(a0), "r"(a1), "r"(a2), "r"(a3), "r"(b0), "r"(b1));
}

// ============================================================================
// k_prep: build w's bf16 hi/lo packed smem image once (all k_node blocks copy it).
// ============================================================================
__global__ void k_prep(const float* __restrict__ w) {
    int i = blockIdx.x * blockDim.x + threadIdx.x;   // 0..2047 pairs
    if (i >= 2048) return;
    int row = i >> 5, cp = i & 31;
    float x = __ldg(&w[row * 64 + 2 * cp]);
    float y = __ldg(&w[row * 64 + 2 * cp + 1]);
    uint32_t ph = pack_bf16x2(x, y);
    float fx = __uint_as_float(ph << 16);
    float fy = __uint_as_float(ph & 0xffff0000u);
    uint32_t pl = pack_bf16x2(x - fx, y - fy);
    g_wimg_hi[row * 36 + cp] = ph;
    g_wimg_lo[row * 36 + cp] = pl;
}

// ============================================================================
// k_node: 64-node x 64-out tile via bf16-split tensor-core MMA (R16-proven
// mainloop). w tiles copied pre-converted from gmem; h converted with the
// cvt.bf16x2 + shift/mask trick (half the prologue instructions of R16).
// ============================================================================
__global__ void __launch_bounds__(128) k_node(
    const float* __restrict__ h, const float* __restrict__ attn) {
    __shared__ uint32_t sH_hi[TILE_M * 36];   // 9KB each
    __shared__ uint32_t sH_lo[TILE_M * 36];
    __shared__ uint32_t sW_hi[64 * 36];
    __shared__ uint32_t sW_lo[64 * 36];

    int tid = threadIdx.x;
    int n0 = blockIdx.x * TILE_M;
    int nrem = N_NODES - n0;              // last block: 16

    // --- w tiles: linear uint4 copy of the precomputed image (L2-resident) ---
    {
        uint4* dhi = reinterpret_cast<uint4*>(sW_hi);
        uint4* dlo = reinterpret_cast<uint4*>(sW_lo);
        const uint4* shi = reinterpret_cast<const uint4*>(g_wimg_hi);
        const uint4* slo = reinterpret_cast<const uint4*>(g_wimg_lo);
        for (int i = tid; i < 1152; i += 128) {
            if (i < 576) dhi[i] = __ldg(shi + i);
            else         dlo[i - 576] = __ldg(slo + i - 576);
        }
    }
    // --- h fill + s/d: 2 threads per row, 32 cols each; fast bf16 split ---
    {
        int row = tid >> 1;
        int half = tid & 1;
        bool valid = (row < nrem);
        const float4* hrow = reinterpret_cast<const float4*>(
            h + (size_t)(n0 + (valid ? row : 0)) * DIM) + half * 8;
        float s = 0.f, d = 0.f;
#pragma unroll
        for (int c4 = 0; c4 < 8; c4++) {
            float4 v = valid ? __ldg(hrow + c4) : make_float4(0.f, 0.f, 0.f, 0.f);
            int cb = half * 32 + c4 * 4;
            s = fmaf(v.x, __ldg(attn + cb), s);
            s = fmaf(v.y, __ldg(attn + cb + 1), s);
            s = fmaf(v.z, __ldg(attn + cb + 2), s);
            s = fmaf(v.w, __ldg(attn + cb + 3), s);
            d = fmaf(v.x, __ldg(attn + 64 + cb), d);
            d = fmaf(v.y, __ldg(attn + 64 + cb + 1), d);
            d = fmaf(v.z, __ldg(attn + 64 + cb + 2), d);
            d = fmaf(v.w, __ldg(attn + 64 + cb + 3), d);
            uint32_t ph0 = pack_bf16x2(v.x, v.y);
            uint32_t ph1 = pack_bf16x2(v.z, v.w);
            float fx = __uint_as_float(ph0 << 16);
            float fy = __uint_as_float(ph0 & 0xffff0000u);
            float fz = __uint_as_float(ph1 << 16);
            float fw = __uint_as_float(ph1 & 0xffff0000u);
            uint32_t pl0 = pack_bf16x2(v.x - fx, v.y - fy);
            uint32_t pl1 = pack_bf16x2(v.z - fz, v.w - fw);
            int idx = row * 36 + cb / 2;
            sH_hi[idx]     = ph0;
            sH_hi[idx + 1] = ph1;
            sH_lo[idx]     = pl0;
            sH_lo[idx + 1] = pl1;
        }
        s += __shfl_xor_sync(0xffffffffu, s, 1);
        d += __shfl_xor_sync(0xffffffffu, d, 1);
        if (half == 0 && valid) {
            int n = n0 + row;
            g_s[n] = s;
            g_d[n] = d;
            g_denom[n] = 0.0f;
            float4 z = make_float4(0.f, 0.f, 0.f, 0.f);
            *reinterpret_cast<float4*>(&g_A[n * 8]) = z;
            *reinterpret_cast<float4*>(&g_A[n * 8 + 4]) = z;
        }
    }
    __syncthreads();

    // --- tensor-core mainloop (R16-proven) ---
    int lane = tid & 31;
    int wid = tid >> 5;                  // 0..3
    int g = lane >> 2;                   // 0..7
    int q = lane & 3;                    // 0..3
    int row0 = wid * 16 + g;

    float acc[8][4];
#pragma unroll
    for (int nt = 0; nt < 8; nt++)
#pragma unroll
        for (int j = 0; j < 4; j++) acc[nt][j] = 0.0f;

#pragma unroll
    for (int kt = 0; kt < 4; kt++) {
        int ai = row0 * 36 + kt * 8 + q;
        uint32_t ah0 = sH_hi[ai],       ah1 = sH_hi[ai + 8 * 36];
        uint32_t ah2 = sH_hi[ai + 4],   ah3 = sH_hi[ai + 4 + 8 * 36];
        uint32_t al0 = sH_lo[ai],       al1 = sH_lo[ai + 8 * 36];
        uint32_t al2 = sH_lo[ai + 4],   al3 = sH_lo[ai + 4 + 8 * 36];
#pragma unroll
        for (int nt = 0; nt < 8; nt++) {
            int bi = (nt * 8 + g) * 36 + kt * 8 + q;
            uint32_t bh0 = sW_hi[bi], bh1 = sW_hi[bi + 4];
            uint32_t bl0 = sW_lo[bi], bl1 = sW_lo[bi + 4];
            mma_bf16(acc[nt], ah0, ah1, ah2, ah3, bh0, bh1);
            mma_bf16(acc[nt], ah0, ah1, ah2, ah3, bl0, bl1);
            mma_bf16(acc[nt], al0, al1, al2, al3, bh0, bh1);
        }
    }

    // --- store p (R16-proven) ---
    {
        int r1 = row0, r2 = row0 + 8;
        bool v1 = (r1 < nrem), v2 = (r2 < nrem);
        float* base1 = &g_p[(size_t)(n0 + r1) * DIM];
        float* base2 = &g_p[(size_t)(n0 + r2) * DIM];
#pragma unroll
        for (int nt = 0; nt < 8; nt++) {
            int col = nt * 8 + q * 2;
            if (v1) *reinterpret_cast<float2*>(base1 + col) =
                        make_float2(acc[nt][0], acc[nt][1]);
            if (v2) *reinterpret_cast<float2*>(base2 + col) =
                        make_float2(acc[nt][2], acc[nt][3]);
        }
    }
}

// ============================================================================
// Fused edge pass (proven): denom[dn] += ex ; A[dn] += ex * p[sn, 8r..8r+7].
// ============================================================================
__global__ void k_edge(const int* __restrict__ src, const int* __restrict__ dst,
                       const int* __restrict__ we) {
    int e = blockIdx.x * blockDim.x + threadIdx.x;
    if (e >= N_EDGES) return;
    int sn = src[e], dn = dst[e], r = we[e];
    float x = __ldg(&g_s[sn]) + __ldg(&g_d[dn]);
    float v = (x > 0.0f) ? x : 0.01f * x;
    float ex = __expf(v);
    const float4* pr = reinterpret_cast<const float4*>(g_p + sn * DIM + r * 8);
    float4 p0 = __ldg(pr), p1 = __ldg(pr + 1);
    atomicAdd(&g_denom[dn], ex);
    float4* arow = reinterpret_cast<float4*>(g_A + dn * 8);
    atomicAdd(&arow[0], make_float4(ex * p0.x, ex * p0.y, ex * p0.z, ex * p0.w));
    atomicAdd(&arow[1], make_float4(ex * p1.x, ex * p1.y, ex * p1.z, ex * p1.w));
}

// ============================================================================
// Expand (proven): out[n, o] = w_comp[o & 7] * A[n, o >> 3] / max(denom, 1e-38).
// ============================================================================
#define HALF_F4 (N_NODES * 8)
__global__ void k_expand(const float* __restrict__ w_comp, float* __restrict__ out) {
    int t = blockIdx.x * blockDim.x + threadIdx.x;
    if (t >= HALF_F4) return;
    float4 wc0 = __ldg(reinterpret_cast<const float4*>(w_comp));
    float4 wc1 = __ldg(reinterpret_cast<const float4*>(w_comp) + 1);
#pragma unroll
    for (int half = 0; half < 2; half++) {
        int t4 = t + half * HALF_F4;
        int n = t4 >> 4;
        int k = t4 & 15;
        float inv = __fdividef(1.0f, fmaxf(g_denom[n], 1e-38f));
        float a = g_A[n * 8 + (k >> 1)] * inv;
        float4 wc = (k & 1) ? wc1 : wc0;
        reinterpret_cast<float4*>(out)[t4] =
            make_float4(a * wc.x, a * wc.y, a * wc.z, a * wc.w);
    }
}

extern "C" void kernel_launch(void* const* d_in, const int* in_sizes, int n_in,
                              void* d_out, int out_size) {
    const float* h      = (const float*)d_in[0];
    const int*   src    = (const int*)d_in[1];
    const int*   dst    = (const int*)d_in[2];
    const int*   we     = (const int*)d_in[3];
    const float* w      = (const float*)d_in[4];
    const float* w_comp = (const float*)d_in[5];
    const float* attn   = (const float*)d_in[6];
    float* out = (float*)d_out;
    (void)in_sizes; (void)n_in; (void)out_size;

    k_prep<<<8, 256>>>(w);
    k_node<<<(N_NODES + TILE_M - 1) / TILE_M, 128>>>(h, attn);
    k_edge<<<(N_EDGES + 255) / 256, 256>>>(src, dst, we);
    k_expand<<<(HALF_F4 + 255) / 256, 256>>>(w_comp, out);
}